// round 14
// baseline (speedup 1.0000x reference)
#include <cuda_runtime.h>
#include <cuda_bf16.h>
#include <mma.h>

using namespace nvcuda;

#define N_NODES 40000
#define N_PAD 40064     // 313 * 128
#define N_EDGES 640000
#define D 128
#define CAP 64          // per-node bucket capacity (deg ~ Poisson(16))
#define XLD 136         // smem bf16 row stride (elements)
#define OLD 132         // epilogue fp32 row stride

// Scratch (device globals — no allocation allowed; zero-init covers pad rows)
__device__ __nv_bfloat16 g_xh[N_PAD * D];   // x hi (rows 40000+ stay zero)
__device__ __nv_bfloat16 g_xl[N_PAD * D];   // x lo
__device__ __nv_bfloat16 g_wh[D * D];       // W hi, native [o][i] layout
__device__ __nv_bfloat16 g_wl[D * D];       // W lo
__device__ int g_cur[N_NODES];              // bucket cursors == in-degree
__device__ int g_bkt[N_NODES * CAP];        // src indices bucketed by dst

__device__ __forceinline__ bool idx_is64(const void* p) {
    const int* q = (const int*)p;
    return ((q[1] | q[3] | q[5] | q[7]) == 0);
}
__device__ __forceinline__ int load_idx(const void* p, int e, bool is64) {
    return is64 ? (int)reinterpret_cast<const long long*>(p)[e]
                : reinterpret_cast<const int*>(p)[e];
}

// ---------------------------------------------------------------------------
// 1) Bucket scatter (R6-proven). Blocks >= 2500 split W into bf16 hi/lo.
// ---------------------------------------------------------------------------
__global__ void __launch_bounds__(256) scatter_kernel(
    const void* __restrict__ src, const void* __restrict__ dst,
    const float* __restrict__ W)
{
    int b = blockIdx.x, t = threadIdx.x;
    if (b >= N_EDGES / 256) {               // 64 W-split blocks
        int idx = (b - N_EDGES / 256) * 256 + t;
        float w = W[idx];
        __nv_bfloat16 h = __float2bfloat16_rn(w);
        g_wh[idx] = h;
        g_wl[idx] = __float2bfloat16_rn(w - __bfloat162float(h));
        return;
    }
    bool is64 = idx_is64(dst);
    int e = b * 256 + t;
    int d = load_idx(dst, e, is64);
    int s = load_idx(src, e, is64);
    int pos = atomicAdd(g_cur + d, 1);
    if (pos < CAP) g_bkt[d * CAP + pos] = s;
}

// ---------------------------------------------------------------------------
// 2) Aggregate: one warp per node; explicit MLP-8 gather batches
//    (8 shuffles -> 8 addresses -> 8 independent LDG.128 -> 2 sum chains).
//    x = feat[d]*sum/max(deg,1), emitted as bf16 hi/lo.
// ---------------------------------------------------------------------------
__global__ void __launch_bounds__(256) agg_kernel(const float* __restrict__ feat)
{
    int n    = (blockIdx.x * 256 + threadIdx.x) >> 5;   // 5000 blocks * 8 warps
    int lane = threadIdx.x & 31;
    if (n >= N_NODES) return;

    int deg = min(g_cur[n], CAP);
    const int* bkt = g_bkt + n * CAP;

    float4 sum0 = make_float4(0.f, 0.f, 0.f, 0.f);
    float4 sum1 = make_float4(0.f, 0.f, 0.f, 0.f);

    for (int base = 0; base < deg; base += 32) {
        int m = min(32, deg - base);
        int myidx = (lane < m) ? bkt[base + lane] : 0;

        int q = 0;
        for (; q + 8 <= m; q += 8) {
            const float4* p[8];
            #pragma unroll
            for (int u = 0; u < 8; ++u) {
                int s = __shfl_sync(0xffffffffu, myidx, q + u);
                p[u] = reinterpret_cast<const float4*>(feat + (size_t)s * D) + lane;
            }
            float4 a[8];
            #pragma unroll
            for (int u = 0; u < 8; ++u) a[u] = *p[u];   // 8 loads in flight
            #pragma unroll
            for (int u = 0; u < 8; ++u) {
                if (u & 1) {
                    sum1.x += a[u].x; sum1.y += a[u].y;
                    sum1.z += a[u].z; sum1.w += a[u].w;
                } else {
                    sum0.x += a[u].x; sum0.y += a[u].y;
                    sum0.z += a[u].z; sum0.w += a[u].w;
                }
            }
        }
        for (; q < m; ++q) {                            // remainder (deg%8)
            int s = __shfl_sync(0xffffffffu, myidx, q);
            float4 a = reinterpret_cast<const float4*>(feat + (size_t)s * D)[lane];
            sum0.x += a.x; sum0.y += a.y; sum0.z += a.z; sum0.w += a.w;
        }
    }

    float inv = 1.0f / (float)max(deg, 1);
    float4 f = reinterpret_cast<const float4*>(feat + (size_t)n * D)[lane];
    float xv[4] = {(sum0.x + sum1.x) * f.x * inv, (sum0.y + sum1.y) * f.y * inv,
                   (sum0.z + sum1.z) * f.z * inv, (sum0.w + sum1.w) * f.w * inv};

    unsigned short hb[4], lb[4];
    #pragma unroll
    for (int i = 0; i < 4; ++i) {
        __nv_bfloat16 h = __float2bfloat16_rn(xv[i]);
        hb[i] = __bfloat16_as_ushort(h);
        lb[i] = __bfloat16_as_ushort(__float2bfloat16_rn(xv[i] - __bfloat162float(h)));
    }
    uint2 hp = make_uint2((unsigned)hb[0] | ((unsigned)hb[1] << 16),
                          (unsigned)hb[2] | ((unsigned)hb[3] << 16));
    uint2 lp = make_uint2((unsigned)lb[0] | ((unsigned)lb[1] << 16),
                          (unsigned)lb[2] | ((unsigned)lb[3] << 16));
    *reinterpret_cast<uint2*>(g_xh + (size_t)n * D + lane * 4) = hp;
    *reinterpret_cast<uint2*>(g_xl + (size_t)n * D + lane * 4) = lp;
}

// ---------------------------------------------------------------------------
// 3) WMMA bf16 GEMM (R13-proven): out = x @ W^T + b.
//    acc = xh*wh + xh*wl + xl*wh (fp32). 313 blocks, 128x128 tile, full K
//    in smem; 8 warps = 2(m) x 4(n), warp tile 64x32.
// ---------------------------------------------------------------------------
__global__ void __launch_bounds__(256) tgemm_kernel(
    const float* __restrict__ bias, float* __restrict__ out)
{
    extern __shared__ char sm[];
    __nv_bfloat16* XH = (__nv_bfloat16*)sm;        // [128][136]
    __nv_bfloat16* XL = XH + D * XLD;
    __nv_bfloat16* WH = XL + D * XLD;              // [n=128][k=136]
    __nv_bfloat16* WL = WH + D * XLD;
    float* OS = (float*)sm;                        // epilogue reuse [128][132]

    const int t    = threadIdx.x;
    const int warp = t >> 5;
    const int r0   = blockIdx.x * 128;             // 313 blocks, rows < 40064

    #pragma unroll
    for (int i = 0; i < 8; ++i) {
        int idx = i * 256 + t;                     // 0..2047
        int row = idx >> 4;                        // 0..127
        int ch  = idx & 15;                        // 16B chunk
        *(uint4*)(XH + row * XLD + ch * 8) =
            *(const uint4*)(g_xh + (size_t)(r0 + row) * D + ch * 8);
        *(uint4*)(XL + row * XLD + ch * 8) =
            *(const uint4*)(g_xl + (size_t)(r0 + row) * D + ch * 8);
        *(uint4*)(WH + row * XLD + ch * 8) =
            *(const uint4*)(g_wh + (size_t)row * D + ch * 8);
        *(uint4*)(WL + row * XLD + ch * 8) =
            *(const uint4*)(g_wl + (size_t)row * D + ch * 8);
    }
    __syncthreads();

    const int wm = warp >> 2;
    const int wn = warp & 3;

    wmma::fragment<wmma::accumulator, 16, 16, 16, float> acc[4][2];
    #pragma unroll
    for (int mi = 0; mi < 4; ++mi)
        #pragma unroll
        for (int ni = 0; ni < 2; ++ni)
            wmma::fill_fragment(acc[mi][ni], 0.0f);

    #pragma unroll
    for (int pass = 0; pass < 3; ++pass) {
        const __nv_bfloat16* A = (pass == 2) ? XL : XH;
        const __nv_bfloat16* B = (pass == 1) ? WL : WH;
        #pragma unroll
        for (int k0 = 0; k0 < D / 16; ++k0) {
            wmma::fragment<wmma::matrix_a, 16, 16, 16, __nv_bfloat16, wmma::row_major> a[4];
            wmma::fragment<wmma::matrix_b, 16, 16, 16, __nv_bfloat16, wmma::col_major> b[2];
            #pragma unroll
            for (int mi = 0; mi < 4; ++mi)
                wmma::load_matrix_sync(a[mi], A + (wm * 64 + mi * 16) * XLD + k0 * 16, XLD);
            #pragma unroll
            for (int ni = 0; ni < 2; ++ni)
                wmma::load_matrix_sync(b[ni], B + (wn * 32 + ni * 16) * XLD + k0 * 16, XLD);
            #pragma unroll
            for (int mi = 0; mi < 4; ++mi)
                #pragma unroll
                for (int ni = 0; ni < 2; ++ni)
                    wmma::mma_sync(acc[mi][ni], a[mi], b[ni], acc[mi][ni]);
        }
    }
    __syncthreads();

    #pragma unroll
    for (int mi = 0; mi < 4; ++mi)
        #pragma unroll
        for (int ni = 0; ni < 2; ++ni)
            wmma::store_matrix_sync(OS + (wm * 64 + mi * 16) * OLD + wn * 32 + ni * 16,
                                    acc[mi][ni], OLD, wmma::mem_row_major);
    __syncthreads();

    #pragma unroll
    for (int i = 0; i < 16; ++i) {
        int idx = i * 256 + t;
        int row = idx >> 5;
        int c4  = idx & 31;
        int r = r0 + row;
        if (r < N_NODES) {
            float4 v = *(const float4*)(OS + row * OLD + c4 * 4);
            float4 bq = *(const float4*)(bias + c4 * 4);
            *(float4*)(out + (size_t)r * D + c4 * 4) =
                make_float4(v.x + bq.x, v.y + bq.y, v.z + bq.z, v.w + bq.w);
        }
    }
}

// ---------------------------------------------------------------------------
extern "C" void kernel_launch(void* const* d_in, const int* in_sizes, int n_in,
                              void* d_out, int out_size) {
    const float* feat = (const float*)d_in[0];
    const void*  src  = d_in[1];
    const void*  dst  = d_in[2];
    const float* W    = (const float*)d_in[3];
    const float* b    = (const float*)d_in[4];
    float*       out  = (float*)d_out;

    void* cur_ptr = nullptr;
    cudaGetSymbolAddress(&cur_ptr, g_cur);

    const int smem_bytes = 4 * D * XLD * sizeof(__nv_bfloat16);   // 139264
    cudaFuncSetAttribute(tgemm_kernel,
                         cudaFuncAttributeMaxDynamicSharedMemorySize, smem_bytes);

    cudaMemsetAsync(cur_ptr, 0, sizeof(int) * N_NODES);

    scatter_kernel<<<N_EDGES / 256 + 64, 256>>>(src, dst, W);  // + W-split blocks
    agg_kernel<<<(N_NODES * 32 + 255) / 256, 256>>>(feat);
    tgemm_kernel<<<N_PAD / 128, 256, smem_bytes>>>(b, out);
}

// round 15
// speedup vs baseline: 1.1090x; 1.1090x over previous
#include <cuda_runtime.h>
#include <cuda_bf16.h>
#include <mma.h>

using namespace nvcuda;

#define N_NODES 40000
#define N_PAD 40064     // 313 * 128
#define N_EDGES 640000
#define D 128
#define CAP 64          // per-node bucket capacity (deg ~ Poisson(16))
#define XLD 136         // smem bf16 row stride (elements)
#define OLD 132         // epilogue fp32 row stride

// Scratch (device globals — no allocation allowed; zero-init covers pad rows)
__device__ __nv_bfloat16 g_xh[N_PAD * D];   // x hi (rows 40000+ stay zero)
__device__ __nv_bfloat16 g_xl[N_PAD * D];   // x lo
__device__ __nv_bfloat16 g_wh[D * D];       // W hi, native [o][i] layout
__device__ __nv_bfloat16 g_wl[D * D];       // W lo
__device__ int g_cur[N_NODES];              // bucket cursors == in-degree
__device__ int g_bkt[N_NODES * CAP];        // src indices bucketed by dst

__device__ __forceinline__ bool idx_is64(const void* p) {
    const int* q = (const int*)p;
    return ((q[1] | q[3] | q[5] | q[7]) == 0);
}
__device__ __forceinline__ int load_idx(const void* p, int e, bool is64) {
    return is64 ? (int)reinterpret_cast<const long long*>(p)[e]
                : reinterpret_cast<const int*>(p)[e];
}

// ---------------------------------------------------------------------------
// 1) Bucket scatter (R6-proven). Blocks >= 2500 split W into bf16 hi/lo.
// ---------------------------------------------------------------------------
__global__ void __launch_bounds__(256) scatter_kernel(
    const void* __restrict__ src, const void* __restrict__ dst,
    const float* __restrict__ W)
{
    int b = blockIdx.x, t = threadIdx.x;
    if (b >= N_EDGES / 256) {               // 64 W-split blocks
        int idx = (b - N_EDGES / 256) * 256 + t;
        float w = W[idx];
        __nv_bfloat16 h = __float2bfloat16_rn(w);
        g_wh[idx] = h;
        g_wl[idx] = __float2bfloat16_rn(w - __bfloat162float(h));
        return;
    }
    bool is64 = idx_is64(dst);
    int e = b * 256 + t;
    int d = load_idx(dst, e, is64);
    int s = load_idx(src, e, is64);
    int pos = atomicAdd(g_cur + d, 1);
    if (pos < CAP) g_bkt[d * CAP + pos] = s;
}

// ---------------------------------------------------------------------------
// 2) Aggregate (R13-exact, proven ~30us = near LTS byte floor): one warp per
//    node, register gather-sum, x = feat[d]*sum/max(deg,1), bf16 hi/lo out.
// ---------------------------------------------------------------------------
__global__ void __launch_bounds__(256) agg_kernel(const float* __restrict__ feat)
{
    int n    = (blockIdx.x * 256 + threadIdx.x) >> 5;   // 5000 blocks * 8 warps
    int lane = threadIdx.x & 31;
    if (n >= N_NODES) return;

    int deg = min(g_cur[n], CAP);
    const int* bkt = g_bkt + n * CAP;

    float4 sum = make_float4(0.f, 0.f, 0.f, 0.f);
    for (int j = 0; j < deg; j += 32) {
        int m = min(32, deg - j);
        int myidx = (lane < m) ? bkt[j + lane] : 0;
        #pragma unroll 4
        for (int q = 0; q < m; ++q) {
            int s = __shfl_sync(0xffffffffu, myidx, q);
            float4 a = reinterpret_cast<const float4*>(feat + (size_t)s * D)[lane];
            sum.x += a.x; sum.y += a.y; sum.z += a.z; sum.w += a.w;
        }
    }

    float inv = 1.0f / (float)max(deg, 1);
    float4 f = reinterpret_cast<const float4*>(feat + (size_t)n * D)[lane];
    float xv[4] = {sum.x * f.x * inv, sum.y * f.y * inv,
                   sum.z * f.z * inv, sum.w * f.w * inv};

    unsigned short hb[4], lb[4];
    #pragma unroll
    for (int i = 0; i < 4; ++i) {
        __nv_bfloat16 h = __float2bfloat16_rn(xv[i]);
        hb[i] = __bfloat16_as_ushort(h);
        lb[i] = __bfloat16_as_ushort(__float2bfloat16_rn(xv[i] - __bfloat162float(h)));
    }
    uint2 hp = make_uint2((unsigned)hb[0] | ((unsigned)hb[1] << 16),
                          (unsigned)hb[2] | ((unsigned)hb[3] << 16));
    uint2 lp = make_uint2((unsigned)lb[0] | ((unsigned)lb[1] << 16),
                          (unsigned)lb[2] | ((unsigned)lb[3] << 16));
    *reinterpret_cast<uint2*>(g_xh + (size_t)n * D + lane * 4) = hp;
    *reinterpret_cast<uint2*>(g_xl + (size_t)n * D + lane * 4) = lp;
}

// ---------------------------------------------------------------------------
// 3) WMMA bf16 GEMM with fused passes (fragment reuse): per k0, load
//    aH/bH/bL, MMA aH*bH + aH*bL, load aL, MMA aL*bH. 12 frag loads per k0
//    vs 18 in the 3-pass form; math identical.
// ---------------------------------------------------------------------------
__global__ void __launch_bounds__(256) tgemm_kernel(
    const float* __restrict__ bias, float* __restrict__ out)
{
    extern __shared__ char sm[];
    __nv_bfloat16* XH = (__nv_bfloat16*)sm;        // [128][136]
    __nv_bfloat16* XL = XH + D * XLD;
    __nv_bfloat16* WH = XL + D * XLD;              // [n=128][k=136]
    __nv_bfloat16* WL = WH + D * XLD;
    float* OS = (float*)sm;                        // epilogue reuse [128][132]

    const int t    = threadIdx.x;
    const int warp = t >> 5;
    const int r0   = blockIdx.x * 128;             // 313 blocks, rows < 40064

    #pragma unroll
    for (int i = 0; i < 8; ++i) {
        int idx = i * 256 + t;                     // 0..2047
        int row = idx >> 4;                        // 0..127
        int ch  = idx & 15;                        // 16B chunk
        *(uint4*)(XH + row * XLD + ch * 8) =
            *(const uint4*)(g_xh + (size_t)(r0 + row) * D + ch * 8);
        *(uint4*)(XL + row * XLD + ch * 8) =
            *(const uint4*)(g_xl + (size_t)(r0 + row) * D + ch * 8);
        *(uint4*)(WH + row * XLD + ch * 8) =
            *(const uint4*)(g_wh + (size_t)row * D + ch * 8);
        *(uint4*)(WL + row * XLD + ch * 8) =
            *(const uint4*)(g_wl + (size_t)row * D + ch * 8);
    }
    __syncthreads();

    const int wm = warp >> 2;                      // m base wm*64
    const int wn = warp & 3;                       // n base wn*32

    wmma::fragment<wmma::accumulator, 16, 16, 16, float> acc[4][2];
    #pragma unroll
    for (int mi = 0; mi < 4; ++mi)
        #pragma unroll
        for (int ni = 0; ni < 2; ++ni)
            wmma::fill_fragment(acc[mi][ni], 0.0f);

    #pragma unroll
    for (int k0 = 0; k0 < D / 16; ++k0) {
        wmma::fragment<wmma::matrix_a, 16, 16, 16, __nv_bfloat16, wmma::row_major> aH[4], aL[4];
        wmma::fragment<wmma::matrix_b, 16, 16, 16, __nv_bfloat16, wmma::col_major> bH[2], bL[2];

        #pragma unroll
        for (int mi = 0; mi < 4; ++mi)
            wmma::load_matrix_sync(aH[mi], XH + (wm * 64 + mi * 16) * XLD + k0 * 16, XLD);
        #pragma unroll
        for (int ni = 0; ni < 2; ++ni) {
            wmma::load_matrix_sync(bH[ni], WH + (wn * 32 + ni * 16) * XLD + k0 * 16, XLD);
            wmma::load_matrix_sync(bL[ni], WL + (wn * 32 + ni * 16) * XLD + k0 * 16, XLD);
        }

        // xh*wh and xh*wl (reuse aH)
        #pragma unroll
        for (int mi = 0; mi < 4; ++mi)
            #pragma unroll
            for (int ni = 0; ni < 2; ++ni) {
                wmma::mma_sync(acc[mi][ni], aH[mi], bH[ni], acc[mi][ni]);
                wmma::mma_sync(acc[mi][ni], aH[mi], bL[ni], acc[mi][ni]);
            }

        // xl*wh (reuse bH)
        #pragma unroll
        for (int mi = 0; mi < 4; ++mi)
            wmma::load_matrix_sync(aL[mi], XL + (wm * 64 + mi * 16) * XLD + k0 * 16, XLD);
        #pragma unroll
        for (int mi = 0; mi < 4; ++mi)
            #pragma unroll
            for (int ni = 0; ni < 2; ++ni)
                wmma::mma_sync(acc[mi][ni], aL[mi], bH[ni], acc[mi][ni]);
    }
    __syncthreads();   // done reading bf16 tiles; smem reused for fp32 out

    #pragma unroll
    for (int mi = 0; mi < 4; ++mi)
        #pragma unroll
        for (int ni = 0; ni < 2; ++ni)
            wmma::store_matrix_sync(OS + (wm * 64 + mi * 16) * OLD + wn * 32 + ni * 16,
                                    acc[mi][ni], OLD, wmma::mem_row_major);
    __syncthreads();

    #pragma unroll
    for (int i = 0; i < 16; ++i) {
        int idx = i * 256 + t;
        int row = idx >> 5;
        int c4  = idx & 31;
        int r = r0 + row;
        if (r < N_NODES) {
            float4 v = *(const float4*)(OS + row * OLD + c4 * 4);
            float4 bq = *(const float4*)(bias + c4 * 4);
            *(float4*)(out + (size_t)r * D + c4 * 4) =
                make_float4(v.x + bq.x, v.y + bq.y, v.z + bq.z, v.w + bq.w);
        }
    }
}

// ---------------------------------------------------------------------------
extern "C" void kernel_launch(void* const* d_in, const int* in_sizes, int n_in,
                              void* d_out, int out_size) {
    const float* feat = (const float*)d_in[0];
    const void*  src  = d_in[1];
    const void*  dst  = d_in[2];
    const float* W    = (const float*)d_in[3];
    const float* b    = (const float*)d_in[4];
    float*       out  = (float*)d_out;

    void* cur_ptr = nullptr;
    cudaGetSymbolAddress(&cur_ptr, g_cur);

    const int smem_bytes = 4 * D * XLD * sizeof(__nv_bfloat16);   // 139264
    cudaFuncSetAttribute(tgemm_kernel,
                         cudaFuncAttributeMaxDynamicSharedMemorySize, smem_bytes);

    cudaMemsetAsync(cur_ptr, 0, sizeof(int) * N_NODES);

    scatter_kernel<<<N_EDGES / 256 + 64, 256>>>(src, dst, W);  // + W-split blocks
    agg_kernel<<<(N_NODES * 32 + 255) / 256, 256>>>(feat);
    tgemm_kernel<<<N_PAD / 128, 256, smem_bytes>>>(b, out);
}